// round 4
// baseline (speedup 1.0000x reference)
#include <cuda_runtime.h>

#define BSZ 8
#define V 4096
#define C 128
#define DK 20
#define TS 1024   // total_samples = V / POOLING_RATE

__device__ float4 g_vq[BSZ * V];
__device__ int    g_sel[BSZ * TS];

// ---------------------------------------------------------------------------
// JAX threefry2x32 block (20 rounds), exact reproduction
// ---------------------------------------------------------------------------
__device__ __forceinline__ void tf2x32(unsigned k0, unsigned k1,
                                       unsigned x0, unsigned x1,
                                       unsigned &o0, unsigned &o1) {
    unsigned ks2 = k0 ^ k1 ^ 0x1BD11BDAu;
#define ROTL(v,d) (((v) << (d)) | ((v) >> (32 - (d))))
#define RND(R) { x0 += x1; x1 = ROTL(x1, R); x1 ^= x0; }
    x0 += k0; x1 += k1;
    RND(13) RND(15) RND(26) RND(6)
    x0 += k1;  x1 += ks2 + 1u;
    RND(17) RND(29) RND(16) RND(24)
    x0 += ks2; x1 += k0 + 2u;
    RND(13) RND(15) RND(26) RND(6)
    x0 += k0;  x1 += k1 + 3u;
    RND(17) RND(29) RND(16) RND(24)
    x0 += k1;  x1 += ks2 + 4u;
    RND(13) RND(15) RND(26) RND(6)
    x0 += ks2; x1 += k0 + 5u;
    o0 = x0; o1 = x1;
#undef RND
#undef ROTL
}

// ---------------------------------------------------------------------------
// Kernel 0: pack vertices into float4 (x, y, z, |v|^2)
// ---------------------------------------------------------------------------
__global__ void pack_kernel(const float* __restrict__ verts) {
    int idx = blockIdx.x * 256 + threadIdx.x;
    if (idx < BSZ * V) {
        float x = verts[idx * 3 + 0];
        float y = verts[idx * 3 + 1];
        float z = verts[idx * 3 + 2];
        float q = __fadd_rn(__fadd_rn(__fmul_rn(x, x), __fmul_rn(y, y)),
                            __fmul_rn(z, z));
        g_vq[idx] = make_float4(x, y, z, q);
    }
}

// ---------------------------------------------------------------------------
// Kernel 1: per-batch density + stratified sampling (1 block / batch)
// ---------------------------------------------------------------------------
__global__ __launch_bounds__(1024)
void sample_kernel(const float* __restrict__ verts, const int* __restrict__ nid) {
    __shared__ unsigned long long keys[V];     // 32 KB (also reused as float scratch)
    __shared__ unsigned char bins[V];          // 4 KB
    __shared__ int cnt[3];
    __shared__ float s_mn, s_mx;
    __shared__ int nsampS[3], cstartS[3], sstartS[3], totS;
    __shared__ unsigned kb0, kb1;

    const int b = blockIdx.x;
    const int tid = threadIdx.x;

    if (tid < 3) cnt[tid] = 0;
    if (tid == 0) {
        // partitionable split: key_b = threefry((0,42), (0, b))
        unsigned o0, o1;
        tf2x32(0u, 42u, 0u, (unsigned)b, o0, o1);
        kb0 = o0; kb1 = o1;
    }

    const float* vb = verts + (size_t)b * V * 3;
    const int* nbv = nid + (size_t)b * V * DK;

    // density s for 4 strided rows per thread (exact fp32 ops, no FMA)
    float sv[4];
#pragma unroll
    for (int m = 0; m < 4; m++) {
        int i = tid + (m << 10);
        float x = vb[i * 3 + 0], y = vb[i * 3 + 1], z = vb[i * 3 + 2];
        float acc = 0.0f;
        for (int k = 0; k < DK; k++) {
            int n = nbv[i * DK + k];
            float dx = __fsub_rn(x, vb[n * 3 + 0]);
            float dy = __fsub_rn(y, vb[n * 3 + 1]);
            float dz = __fsub_rn(z, vb[n * 3 + 2]);
            float sq = __fadd_rn(__fadd_rn(__fmul_rn(dx, dx), __fmul_rn(dy, dy)),
                                 __fmul_rn(dz, dz));
            acc = __fadd_rn(acc, sqrtf(sq));
        }
        sv[m] = acc;
    }

    // block min / max of s
    float* red = (float*)keys;
    float lm = fminf(fminf(sv[0], sv[1]), fminf(sv[2], sv[3]));
    red[tid] = lm; __syncthreads();
    for (int off = 512; off; off >>= 1) {
        if (tid < off) red[tid] = fminf(red[tid], red[tid + off]);
        __syncthreads();
    }
    if (tid == 0) s_mn = red[0];
    __syncthreads();
    float lx = fmaxf(fmaxf(sv[0], sv[1]), fmaxf(sv[2], sv[3]));
    red[tid] = lx; __syncthreads();
    for (int off = 512; off; off >>= 1) {
        if (tid < off) red[tid] = fmaxf(red[tid], red[tid + off]);
        __syncthreads();
    }
    if (tid == 0) s_mx = red[0];
    __syncthreads();

    const float mn = s_mn;
    const float span = __fsub_rn(s_mx, mn);
    const unsigned K0 = kb0, K1 = kb1;
    const float E1 = __uint_as_float(0x3EAAAAABu);  // linspace edge 1/3
    const float E2 = __uint_as_float(0x3F2AAAABu);  // linspace edge 2/3

#pragma unroll
    for (int m = 0; m < 4; m++) {
        int i = tid + (m << 10);
        float nd = __fdiv_rn(__fsub_rn(sv[m], mn), span);
        int bc = (nd > 0.0f) + (nd > E1) + (nd > E2) + (nd > 1.0f);
        bins[i] = (unsigned char)bc;
        if (bc >= 1) atomicAdd(&cnt[bc - 1], 1);
        // uniform u[i]: partitionable bits = o0 ^ o1 of block(key_b, (0, i))
        unsigned r0, r1;
        tf2x32(K0, K1, 0u, (unsigned)i, r0, r1);
        unsigned bits = r0 ^ r1;
        float u = __uint_as_float((bits >> 9) | 0x3F800000u) - 1.0f;
        float skey = (bc == 0) ? (4.0f + u) : ((float)bc + u);
        keys[i] = ((unsigned long long)__float_as_uint(skey) << 32) | (unsigned)i;
    }
    __syncthreads();

    if (tid == 0) {
        int c0 = cnt[0], c1 = cnt[1], c2 = cnt[2];
        float sf = (float)(c0 + c1 + c2);
        int n0 = (int)floorf(__fmul_rn(__fdiv_rn((float)c0, sf), 1024.0f));
        int n1 = (int)floorf(__fmul_rn(__fdiv_rn((float)c1, sf), 1024.0f));
        int n2 = (int)floorf(__fmul_rn(__fdiv_rn((float)c2, sf), 1024.0f));
        nsampS[0] = n0; nsampS[1] = n1; nsampS[2] = n2;
        cstartS[0] = 0; cstartS[1] = c0; cstartS[2] = c0 + c1;
        sstartS[0] = 0; sstartS[1] = n0; sstartS[2] = n0 + n1;
        totS = n0 + n1 + n2;
    }
    __syncthreads();

    // bitonic sort (ascending), 4096 unique uint64 keys
    for (unsigned k = 2; k <= V; k <<= 1) {
        for (unsigned j = k >> 1; j; j >>= 1) {
#pragma unroll
            for (int m = 0; m < 4; m++) {
                unsigned i = (unsigned)tid + ((unsigned)m << 10);
                unsigned p = i ^ j;
                if (p > i) {
                    unsigned long long a = keys[i], c = keys[p];
                    bool up = ((i & k) == 0);
                    if ((a > c) == up) { keys[i] = c; keys[p] = a; }
                }
            }
            __syncthreads();
        }
    }

    int* selb = g_sel + b * TS;
    if (tid >= totS) selb[tid] = 0;   // zeros fill the unsampled tail
#pragma unroll
    for (int m = 0; m < 4; m++) {
        int r = tid + (m << 10);
        int idx = (int)(unsigned)(keys[r] & 0xFFFFFFFFull);
        int sb = bins[idx];
        if (sb >= 1) {
            int bi = sb - 1;
            int rank = r - cstartS[bi];
            if (rank < nsampS[bi]) selb[sstartS[bi] + rank] = idx;
        }
    }
}

// ---------------------------------------------------------------------------
// Kernel 2: KNN (top-5 incl. self) + feature max-pool, selected rows only.
// grid = (TS, BSZ), 128 threads/block.
// ---------------------------------------------------------------------------
__global__ __launch_bounds__(128)
void knn_pool_kernel(const float* __restrict__ verts,
                     const float* __restrict__ fmap,
                     float* __restrict__ out) {
    __shared__ unsigned long long sh[128];
    __shared__ int nbS[5];

    const int b = blockIdx.y;
    const int t = blockIdx.x;
    const int tid = threadIdx.x;

    const int i = g_sel[b * TS + t];
    const float4* vq = g_vq + b * V;
    const float4 vi = vq[i];

    unsigned long long loc[5] = { ~0ull, ~0ull, ~0ull, ~0ull, ~0ull };

#pragma unroll 4
    for (int it = 0; it < 32; ++it) {
        int j = tid + (it << 7);
        float4 vj = vq[j];
        float inner = fmaf(vi.z, vj.z, fmaf(vi.y, vj.y, vi.x * vj.x));
        float dist = fmaf(-2.0f, inner, vi.w) + vj.w;   // ((-2*inner)+qi)+qj
        unsigned db = __float_as_uint(dist);
        db = ((int)db < 0) ? ~db : (db | 0x80000000u);  // order-preserving map
        unsigned long long key = ((unsigned long long)db << 32) | (unsigned)j;
        if (key < loc[4]) {
            loc[4] = key;
#pragma unroll
            for (int q = 4; q > 0; --q) {
                if (loc[q] < loc[q - 1]) {
                    unsigned long long tmp = loc[q - 1];
                    loc[q - 1] = loc[q];
                    loc[q] = tmp;
                }
            }
        }
    }

    // 5-round block-wide min extraction (keys unique)
    for (int r = 0; r < 5; r++) {
        sh[tid] = loc[0];
        __syncthreads();
        for (int off = 64; off; off >>= 1) {
            if (tid < off) {
                unsigned long long o = sh[tid + off];
                if (o < sh[tid]) sh[tid] = o;
            }
            __syncthreads();
        }
        unsigned long long mkey = sh[0];
        __syncthreads();
        if (loc[0] == mkey) {
            loc[0] = loc[1]; loc[1] = loc[2]; loc[2] = loc[3]; loc[3] = loc[4];
            loc[4] = ~0ull;
        }
        if (tid == 0) nbS[r] = (int)(unsigned)(mkey & 0xFFFFFFFFull);
    }
    __syncthreads();

    // nbS[0] is self (dist exactly 0 under this formula); pool over nbS[1..4]
    const int n1 = nbS[1], n2 = nbS[2], n3 = nbS[3], n4 = nbS[4];
    const float* f = fmap + (size_t)b * V * C;
    float mval = fmaxf(fmaxf(f[(size_t)n1 * C + tid], f[(size_t)n2 * C + tid]),
                       fmaxf(f[(size_t)n3 * C + tid], f[(size_t)n4 * C + tid]));

    float* out_v = out;                       // (8, 1024, 3)
    float* out_f = out + BSZ * TS * 3;        // (8, 1024, 128)
    out_f[(size_t)(b * TS + t) * C + tid] = mval;
    if (tid < 3)
        out_v[(b * TS + t) * 3 + tid] = verts[((size_t)b * V + i) * 3 + tid];
}

// ---------------------------------------------------------------------------
extern "C" void kernel_launch(void* const* d_in, const int* in_sizes, int n_in,
                              void* d_out, int out_size) {
    const float* verts = (const float*)d_in[0];
    const float* fmap  = (const float*)d_in[1];
    const int*   nid   = (const int*)d_in[2];
    float* out = (float*)d_out;

    pack_kernel<<<(BSZ * V + 255) / 256, 256>>>(verts);
    sample_kernel<<<BSZ, 1024>>>(verts, nid);
    dim3 g(TS, BSZ);
    knn_pool_kernel<<<g, 128>>>(verts, fmap, out);
}

// round 5
// speedup vs baseline: 1.0013x; 1.0013x over previous
#include <cuda_runtime.h>

#define BSZ 8
#define V 4096
#define C 128
#define DK 20
#define TS 1024   // total_samples = V / POOLING_RATE

__device__ float4 g_vq[BSZ * V];
__device__ int    g_sel[BSZ * TS];

// ---------------------------------------------------------------------------
// JAX threefry2x32 block (20 rounds), exact reproduction
// ---------------------------------------------------------------------------
__device__ __forceinline__ void tf2x32(unsigned k0, unsigned k1,
                                       unsigned x0, unsigned x1,
                                       unsigned &o0, unsigned &o1) {
    unsigned ks2 = k0 ^ k1 ^ 0x1BD11BDAu;
#define ROTL(v,d) (((v) << (d)) | ((v) >> (32 - (d))))
#define RND(R) { x0 += x1; x1 = ROTL(x1, R); x1 ^= x0; }
    x0 += k0; x1 += k1;
    RND(13) RND(15) RND(26) RND(6)
    x0 += k1;  x1 += ks2 + 1u;
    RND(17) RND(29) RND(16) RND(24)
    x0 += ks2; x1 += k0 + 2u;
    RND(13) RND(15) RND(26) RND(6)
    x0 += k0;  x1 += k1 + 3u;
    RND(17) RND(29) RND(16) RND(24)
    x0 += k1;  x1 += ks2 + 4u;
    RND(13) RND(15) RND(26) RND(6)
    x0 += ks2; x1 += k0 + 5u;
    o0 = x0; o1 = x1;
#undef RND
#undef ROTL
}

// ---------------------------------------------------------------------------
// Kernel 0: pack vertices into float4 (x, y, z, |v|^2)
// ---------------------------------------------------------------------------
__global__ void pack_kernel(const float* __restrict__ verts) {
    int idx = blockIdx.x * 256 + threadIdx.x;
    if (idx < BSZ * V) {
        float x = verts[idx * 3 + 0];
        float y = verts[idx * 3 + 1];
        float z = verts[idx * 3 + 2];
        float q = __fadd_rn(__fadd_rn(__fmul_rn(x, x), __fmul_rn(y, y)),
                            __fmul_rn(z, z));
        g_vq[idx] = make_float4(x, y, z, q);
    }
}

// ---------------------------------------------------------------------------
// Kernel 1: per-batch density + stratified sampling (1 block / batch)
// ---------------------------------------------------------------------------
__global__ __launch_bounds__(1024)
void sample_kernel(const float* __restrict__ verts, const int* __restrict__ nid) {
    __shared__ unsigned long long keys[V];     // 32 KB (also reused as float scratch)
    __shared__ unsigned char bins[V];          // 4 KB
    __shared__ int cnt[3];
    __shared__ float s_mn, s_mx;
    __shared__ int nsampS[3], cstartS[3], sstartS[3], totS;
    __shared__ unsigned kb0, kb1;

    const int b = blockIdx.x;
    const int tid = threadIdx.x;

    if (tid < 3) cnt[tid] = 0;
    if (tid == 0) {
        // partitionable split: key_b = threefry((0,42), (0, b))
        unsigned o0, o1;
        tf2x32(0u, 42u, 0u, (unsigned)b, o0, o1);
        kb0 = o0; kb1 = o1;
    }

    const float* vb = verts + (size_t)b * V * 3;
    const int* nbv = nid + (size_t)b * V * DK;

    // density s for 4 strided rows per thread (exact fp32 ops, no FMA)
    float sv[4];
#pragma unroll
    for (int m = 0; m < 4; m++) {
        int i = tid + (m << 10);
        float x = vb[i * 3 + 0], y = vb[i * 3 + 1], z = vb[i * 3 + 2];
        float acc = 0.0f;
        for (int k = 0; k < DK; k++) {
            int n = nbv[i * DK + k];
            float dx = __fsub_rn(x, vb[n * 3 + 0]);
            float dy = __fsub_rn(y, vb[n * 3 + 1]);
            float dz = __fsub_rn(z, vb[n * 3 + 2]);
            float sq = __fadd_rn(__fadd_rn(__fmul_rn(dx, dx), __fmul_rn(dy, dy)),
                                 __fmul_rn(dz, dz));
            acc = __fadd_rn(acc, sqrtf(sq));
        }
        sv[m] = acc;
    }

    // block min / max of s
    float* red = (float*)keys;
    float lm = fminf(fminf(sv[0], sv[1]), fminf(sv[2], sv[3]));
    red[tid] = lm; __syncthreads();
    for (int off = 512; off; off >>= 1) {
        if (tid < off) red[tid] = fminf(red[tid], red[tid + off]);
        __syncthreads();
    }
    if (tid == 0) s_mn = red[0];
    __syncthreads();
    float lx = fmaxf(fmaxf(sv[0], sv[1]), fmaxf(sv[2], sv[3]));
    red[tid] = lx; __syncthreads();
    for (int off = 512; off; off >>= 1) {
        if (tid < off) red[tid] = fmaxf(red[tid], red[tid + off]);
        __syncthreads();
    }
    if (tid == 0) s_mx = red[0];
    __syncthreads();

    const float mn = s_mn;
    const float span = __fsub_rn(s_mx, mn);
    const unsigned K0 = kb0, K1 = kb1;
    const float E1 = __uint_as_float(0x3EAAAAABu);  // linspace edge 1/3
    const float E2 = __uint_as_float(0x3F2AAAABu);  // linspace edge 2/3

#pragma unroll
    for (int m = 0; m < 4; m++) {
        int i = tid + (m << 10);
        float nd = __fdiv_rn(__fsub_rn(sv[m], mn), span);
        int bc = (nd > 0.0f) + (nd > E1) + (nd > E2) + (nd > 1.0f);
        bins[i] = (unsigned char)bc;
        if (bc >= 1) atomicAdd(&cnt[bc - 1], 1);
        // uniform u[i]: partitionable bits = o0 ^ o1 of block(key_b, (0, i))
        unsigned r0, r1;
        tf2x32(K0, K1, 0u, (unsigned)i, r0, r1);
        unsigned bits = r0 ^ r1;
        float u = __uint_as_float((bits >> 9) | 0x3F800000u) - 1.0f;
        float skey = (bc == 0) ? (4.0f + u) : ((float)bc + u);
        keys[i] = ((unsigned long long)__float_as_uint(skey) << 32) | (unsigned)i;
    }
    __syncthreads();

    if (tid == 0) {
        int c0 = cnt[0], c1 = cnt[1], c2 = cnt[2];
        float sf = (float)(c0 + c1 + c2);
        int n0 = (int)floorf(__fmul_rn(__fdiv_rn((float)c0, sf), 1024.0f));
        int n1 = (int)floorf(__fmul_rn(__fdiv_rn((float)c1, sf), 1024.0f));
        int n2 = (int)floorf(__fmul_rn(__fdiv_rn((float)c2, sf), 1024.0f));
        nsampS[0] = n0; nsampS[1] = n1; nsampS[2] = n2;
        cstartS[0] = 0; cstartS[1] = c0; cstartS[2] = c0 + c1;
        sstartS[0] = 0; sstartS[1] = n0; sstartS[2] = n0 + n1;
        totS = n0 + n1 + n2;
    }
    __syncthreads();

    // bitonic sort (ascending), 4096 unique uint64 keys
    for (unsigned k = 2; k <= V; k <<= 1) {
        for (unsigned j = k >> 1; j; j >>= 1) {
#pragma unroll
            for (int m = 0; m < 4; m++) {
                unsigned i = (unsigned)tid + ((unsigned)m << 10);
                unsigned p = i ^ j;
                if (p > i) {
                    unsigned long long a = keys[i], c = keys[p];
                    bool up = ((i & k) == 0);
                    if ((a > c) == up) { keys[i] = c; keys[p] = a; }
                }
            }
            __syncthreads();
        }
    }

    int* selb = g_sel + b * TS;
    if (tid >= totS) selb[tid] = 0;   // zeros fill the unsampled tail
#pragma unroll
    for (int m = 0; m < 4; m++) {
        int r = tid + (m << 10);
        int idx = (int)(unsigned)(keys[r] & 0xFFFFFFFFull);
        int sb = bins[idx];
        if (sb >= 1) {
            int bi = sb - 1;
            int rank = r - cstartS[bi];
            if (rank < nsampS[bi]) selb[sstartS[bi] + rank] = idx;
        }
    }
}

// ---------------------------------------------------------------------------
// Kernel 2: KNN (top-5 incl. self) + feature max-pool, selected rows only.
// grid = (TS, BSZ), 128 threads/block.
// ---------------------------------------------------------------------------
__global__ __launch_bounds__(128)
void knn_pool_kernel(const float* __restrict__ verts,
                     const float* __restrict__ fmap,
                     float* __restrict__ out) {
    __shared__ unsigned long long sh[128];
    __shared__ int nbS[5];

    const int b = blockIdx.y;
    const int t = blockIdx.x;
    const int tid = threadIdx.x;

    const int i = g_sel[b * TS + t];
    const float4* vq = g_vq + b * V;
    const float4 vi = vq[i];

    unsigned long long loc[5] = { ~0ull, ~0ull, ~0ull, ~0ull, ~0ull };

#pragma unroll 4
    for (int it = 0; it < 32; ++it) {
        int j = tid + (it << 7);
        float4 vj = vq[j];
        float inner = fmaf(vi.z, vj.z, fmaf(vi.y, vj.y, vi.x * vj.x));
        float dist = fmaf(-2.0f, inner, vi.w) + vj.w;   // ((-2*inner)+qi)+qj
        unsigned db = __float_as_uint(dist);
        db = ((int)db < 0) ? ~db : (db | 0x80000000u);  // order-preserving map
        unsigned long long key = ((unsigned long long)db << 32) | (unsigned)j;
        if (key < loc[4]) {
            loc[4] = key;
#pragma unroll
            for (int q = 4; q > 0; --q) {
                if (loc[q] < loc[q - 1]) {
                    unsigned long long tmp = loc[q - 1];
                    loc[q - 1] = loc[q];
                    loc[q] = tmp;
                }
            }
        }
    }

    // 5-round block-wide min extraction (keys unique)
    for (int r = 0; r < 5; r++) {
        sh[tid] = loc[0];
        __syncthreads();
        for (int off = 64; off; off >>= 1) {
            if (tid < off) {
                unsigned long long o = sh[tid + off];
                if (o < sh[tid]) sh[tid] = o;
            }
            __syncthreads();
        }
        unsigned long long mkey = sh[0];
        __syncthreads();
        if (loc[0] == mkey) {
            loc[0] = loc[1]; loc[1] = loc[2]; loc[2] = loc[3]; loc[3] = loc[4];
            loc[4] = ~0ull;
        }
        if (tid == 0) nbS[r] = (int)(unsigned)(mkey & 0xFFFFFFFFull);
    }
    __syncthreads();

    // nbS[0] is self (dist exactly 0 under this formula); pool over nbS[1..4]
    const int n1 = nbS[1], n2 = nbS[2], n3 = nbS[3], n4 = nbS[4];
    const float* f = fmap + (size_t)b * V * C;
    float mval = fmaxf(fmaxf(f[(size_t)n1 * C + tid], f[(size_t)n2 * C + tid]),
                       fmaxf(f[(size_t)n3 * C + tid], f[(size_t)n4 * C + tid]));

    float* out_v = out;                       // (8, 1024, 3)
    float* out_f = out + BSZ * TS * 3;        // (8, 1024, 128)
    out_f[(size_t)(b * TS + t) * C + tid] = mval;
    if (tid < 3)
        out_v[(b * TS + t) * 3 + tid] = verts[((size_t)b * V + i) * 3 + tid];
}

// ---------------------------------------------------------------------------
extern "C" void kernel_launch(void* const* d_in, const int* in_sizes, int n_in,
                              void* d_out, int out_size) {
    const float* verts = (const float*)d_in[0];
    const float* fmap  = (const float*)d_in[1];
    const int*   nid   = (const int*)d_in[2];
    float* out = (float*)d_out;

    pack_kernel<<<(BSZ * V + 255) / 256, 256>>>(verts);
    sample_kernel<<<BSZ, 1024>>>(verts, nid);
    dim3 g(TS, BSZ);
    knn_pool_kernel<<<g, 128>>>(verts, fmap, out);
}

// round 6
// speedup vs baseline: 1.0033x; 1.0020x over previous
#include <cuda_runtime.h>

#define BSZ 8
#define V 4096
#define C 128
#define DK 20
#define TS 1024   // total_samples = V / POOLING_RATE

__device__ float4 g_vq[BSZ * V];
__device__ int    g_sel[BSZ * TS];

// ---------------------------------------------------------------------------
// JAX threefry2x32 block (20 rounds), exact reproduction
// ---------------------------------------------------------------------------
__device__ __forceinline__ void tf2x32(unsigned k0, unsigned k1,
                                       unsigned x0, unsigned x1,
                                       unsigned &o0, unsigned &o1) {
    unsigned ks2 = k0 ^ k1 ^ 0x1BD11BDAu;
#define ROTL(v,d) (((v) << (d)) | ((v) >> (32 - (d))))
#define RND(R) { x0 += x1; x1 = ROTL(x1, R); x1 ^= x0; }
    x0 += k0; x1 += k1;
    RND(13) RND(15) RND(26) RND(6)
    x0 += k1;  x1 += ks2 + 1u;
    RND(17) RND(29) RND(16) RND(24)
    x0 += ks2; x1 += k0 + 2u;
    RND(13) RND(15) RND(26) RND(6)
    x0 += k0;  x1 += k1 + 3u;
    RND(17) RND(29) RND(16) RND(24)
    x0 += k1;  x1 += ks2 + 4u;
    RND(13) RND(15) RND(26) RND(6)
    x0 += ks2; x1 += k0 + 5u;
    o0 = x0; o1 = x1;
#undef RND
#undef ROTL
}

// ---------------------------------------------------------------------------
// Kernel 0: pack vertices into float4 (x, y, z, |v|^2)
// ---------------------------------------------------------------------------
__global__ void pack_kernel(const float* __restrict__ verts) {
    int idx = blockIdx.x * 256 + threadIdx.x;
    if (idx < BSZ * V) {
        float x = verts[idx * 3 + 0];
        float y = verts[idx * 3 + 1];
        float z = verts[idx * 3 + 2];
        float q = __fadd_rn(__fadd_rn(__fmul_rn(x, x), __fmul_rn(y, y)),
                            __fmul_rn(z, z));
        g_vq[idx] = make_float4(x, y, z, q);
    }
}

// ---------------------------------------------------------------------------
// Kernel 1: per-batch density + stratified sampling (1 block / batch)
// ---------------------------------------------------------------------------
__global__ __launch_bounds__(1024)
void sample_kernel(const float* __restrict__ verts, const int* __restrict__ nid) {
    __shared__ unsigned long long keys[V];     // 32 KB (also reused as float scratch)
    __shared__ unsigned char bins[V];          // 4 KB
    __shared__ int cnt[3];
    __shared__ float s_mn, s_mx;
    __shared__ int nsampS[3], cstartS[3], sstartS[3], totS;
    __shared__ unsigned kb0, kb1;

    const int b = blockIdx.x;
    const int tid = threadIdx.x;

    if (tid < 3) cnt[tid] = 0;
    if (tid == 0) {
        // partitionable split: key_b = threefry((0,42), (0, b))
        unsigned o0, o1;
        tf2x32(0u, 42u, 0u, (unsigned)b, o0, o1);
        kb0 = o0; kb1 = o1;
    }

    const float* vb = verts + (size_t)b * V * 3;
    const int* nbv = nid + (size_t)b * V * DK;

    // density s for 4 strided rows per thread (exact fp32 ops, no FMA)
    float sv[4];
#pragma unroll
    for (int m = 0; m < 4; m++) {
        int i = tid + (m << 10);
        float x = vb[i * 3 + 0], y = vb[i * 3 + 1], z = vb[i * 3 + 2];
        float acc = 0.0f;
        for (int k = 0; k < DK; k++) {
            int n = nbv[i * DK + k];
            float dx = __fsub_rn(x, vb[n * 3 + 0]);
            float dy = __fsub_rn(y, vb[n * 3 + 1]);
            float dz = __fsub_rn(z, vb[n * 3 + 2]);
            float sq = __fadd_rn(__fadd_rn(__fmul_rn(dx, dx), __fmul_rn(dy, dy)),
                                 __fmul_rn(dz, dz));
            acc = __fadd_rn(acc, sqrtf(sq));
        }
        sv[m] = acc;
    }

    // block min / max of s
    float* red = (float*)keys;
    float lm = fminf(fminf(sv[0], sv[1]), fminf(sv[2], sv[3]));
    red[tid] = lm; __syncthreads();
    for (int off = 512; off; off >>= 1) {
        if (tid < off) red[tid] = fminf(red[tid], red[tid + off]);
        __syncthreads();
    }
    if (tid == 0) s_mn = red[0];
    __syncthreads();
    float lx = fmaxf(fmaxf(sv[0], sv[1]), fmaxf(sv[2], sv[3]));
    red[tid] = lx; __syncthreads();
    for (int off = 512; off; off >>= 1) {
        if (tid < off) red[tid] = fmaxf(red[tid], red[tid + off]);
        __syncthreads();
    }
    if (tid == 0) s_mx = red[0];
    __syncthreads();

    const float mn = s_mn;
    const float span = __fsub_rn(s_mx, mn);
    const unsigned K0 = kb0, K1 = kb1;
    const float E1 = __uint_as_float(0x3EAAAAABu);  // linspace edge 1/3
    const float E2 = __uint_as_float(0x3F2AAAABu);  // linspace edge 2/3

#pragma unroll
    for (int m = 0; m < 4; m++) {
        int i = tid + (m << 10);
        float nd = __fdiv_rn(__fsub_rn(sv[m], mn), span);
        int bc = (nd > 0.0f) + (nd > E1) + (nd > E2) + (nd > 1.0f);
        bins[i] = (unsigned char)bc;
        if (bc >= 1) atomicAdd(&cnt[bc - 1], 1);
        // uniform u[i]: partitionable bits = o0 ^ o1 of block(key_b, (0, i))
        unsigned r0, r1;
        tf2x32(K0, K1, 0u, (unsigned)i, r0, r1);
        unsigned bits = r0 ^ r1;
        float u = __uint_as_float((bits >> 9) | 0x3F800000u) - 1.0f;
        float skey = (bc == 0) ? (4.0f + u) : ((float)bc + u);
        keys[i] = ((unsigned long long)__float_as_uint(skey) << 32) | (unsigned)i;
    }
    __syncthreads();

    if (tid == 0) {
        int c0 = cnt[0], c1 = cnt[1], c2 = cnt[2];
        float sf = (float)(c0 + c1 + c2);
        int n0 = (int)floorf(__fmul_rn(__fdiv_rn((float)c0, sf), 1024.0f));
        int n1 = (int)floorf(__fmul_rn(__fdiv_rn((float)c1, sf), 1024.0f));
        int n2 = (int)floorf(__fmul_rn(__fdiv_rn((float)c2, sf), 1024.0f));
        nsampS[0] = n0; nsampS[1] = n1; nsampS[2] = n2;
        cstartS[0] = 0; cstartS[1] = c0; cstartS[2] = c0 + c1;
        sstartS[0] = 0; sstartS[1] = n0; sstartS[2] = n0 + n1;
        totS = n0 + n1 + n2;
    }
    __syncthreads();

    // bitonic sort (ascending), 4096 unique uint64 keys
    for (unsigned k = 2; k <= V; k <<= 1) {
        for (unsigned j = k >> 1; j; j >>= 1) {
#pragma unroll
            for (int m = 0; m < 4; m++) {
                unsigned i = (unsigned)tid + ((unsigned)m << 10);
                unsigned p = i ^ j;
                if (p > i) {
                    unsigned long long a = keys[i], c = keys[p];
                    bool up = ((i & k) == 0);
                    if ((a > c) == up) { keys[i] = c; keys[p] = a; }
                }
            }
            __syncthreads();
        }
    }

    int* selb = g_sel + b * TS;
    if (tid >= totS) selb[tid] = 0;   // zeros fill the unsampled tail
#pragma unroll
    for (int m = 0; m < 4; m++) {
        int r = tid + (m << 10);
        int idx = (int)(unsigned)(keys[r] & 0xFFFFFFFFull);
        int sb = bins[idx];
        if (sb >= 1) {
            int bi = sb - 1;
            int rank = r - cstartS[bi];
            if (rank < nsampS[bi]) selb[sstartS[bi] + rank] = idx;
        }
    }
}

// ---------------------------------------------------------------------------
// Kernel 2: KNN (top-5 incl. self) + feature max-pool, selected rows only.
// grid = (TS, BSZ), 128 threads/block.
// ---------------------------------------------------------------------------
__global__ __launch_bounds__(128)
void knn_pool_kernel(const float* __restrict__ verts,
                     const float* __restrict__ fmap,
                     float* __restrict__ out) {
    __shared__ unsigned long long sh[128];
    __shared__ int nbS[5];

    const int b = blockIdx.y;
    const int t = blockIdx.x;
    const int tid = threadIdx.x;

    const int i = g_sel[b * TS + t];
    const float4* vq = g_vq + b * V;
    const float4 vi = vq[i];

    unsigned long long loc[5] = { ~0ull, ~0ull, ~0ull, ~0ull, ~0ull };

#pragma unroll 4
    for (int it = 0; it < 32; ++it) {
        int j = tid + (it << 7);
        float4 vj = vq[j];
        float inner = fmaf(vi.z, vj.z, fmaf(vi.y, vj.y, vi.x * vj.x));
        float dist = fmaf(-2.0f, inner, vi.w) + vj.w;   // ((-2*inner)+qi)+qj
        unsigned db = __float_as_uint(dist);
        db = ((int)db < 0) ? ~db : (db | 0x80000000u);  // order-preserving map
        unsigned long long key = ((unsigned long long)db << 32) | (unsigned)j;
        if (key < loc[4]) {
            loc[4] = key;
#pragma unroll
            for (int q = 4; q > 0; --q) {
                if (loc[q] < loc[q - 1]) {
                    unsigned long long tmp = loc[q - 1];
                    loc[q - 1] = loc[q];
                    loc[q] = tmp;
                }
            }
        }
    }

    // 5-round block-wide min extraction (keys unique)
    for (int r = 0; r < 5; r++) {
        sh[tid] = loc[0];
        __syncthreads();
        for (int off = 64; off; off >>= 1) {
            if (tid < off) {
                unsigned long long o = sh[tid + off];
                if (o < sh[tid]) sh[tid] = o;
            }
            __syncthreads();
        }
        unsigned long long mkey = sh[0];
        __syncthreads();
        if (loc[0] == mkey) {
            loc[0] = loc[1]; loc[1] = loc[2]; loc[2] = loc[3]; loc[3] = loc[4];
            loc[4] = ~0ull;
        }
        if (tid == 0) nbS[r] = (int)(unsigned)(mkey & 0xFFFFFFFFull);
    }
    __syncthreads();

    // nbS[0] is self (dist exactly 0 under this formula); pool over nbS[1..4]
    const int n1 = nbS[1], n2 = nbS[2], n3 = nbS[3], n4 = nbS[4];
    const float* f = fmap + (size_t)b * V * C;
    float mval = fmaxf(fmaxf(f[(size_t)n1 * C + tid], f[(size_t)n2 * C + tid]),
                       fmaxf(f[(size_t)n3 * C + tid], f[(size_t)n4 * C + tid]));

    float* out_v = out;                       // (8, 1024, 3)
    float* out_f = out + BSZ * TS * 3;        // (8, 1024, 128)
    out_f[(size_t)(b * TS + t) * C + tid] = mval;
    if (tid < 3)
        out_v[(b * TS + t) * 3 + tid] = verts[((size_t)b * V + i) * 3 + tid];
}

// ---------------------------------------------------------------------------
extern "C" void kernel_launch(void* const* d_in, const int* in_sizes, int n_in,
                              void* d_out, int out_size) {
    const float* verts = (const float*)d_in[0];
    const float* fmap  = (const float*)d_in[1];
    const int*   nid   = (const int*)d_in[2];
    float* out = (float*)d_out;

    pack_kernel<<<(BSZ * V + 255) / 256, 256>>>(verts);
    sample_kernel<<<BSZ, 1024>>>(verts, nid);
    dim3 g(TS, BSZ);
    knn_pool_kernel<<<g, 128>>>(verts, fmap, out);
}